// round 3
// baseline (speedup 1.0000x reference)
#include <cuda_runtime.h>
#include <math.h>

#define BATCH   32
#define DDIM    256
#define HWSZ    1024
#define NROWS   32768
#define KCODES  1024
#define QELEMS  8388608      // 32*256*32*32
#define ENC_ELEMS 33554432   // 32768*1024

#define TM 128
#define TN 64
#define BK 16
#define NT (KCODES / TN)     // 16 column tiles
#define NTHREADS 256

// scratch (module-scope device globals: allowed; no allocations)
__device__ float g_wnorm[KCODES];
__device__ float g_probs[KCODES];
__device__ float g_loss;

// ---------------------------------------------------------------------------
// Init: zero accumulators, compute ||W_k||^2 per code (one warp per code)
// ---------------------------------------------------------------------------
__global__ void vq_init(const float* __restrict__ W) {
    int gt = blockIdx.x * 256 + threadIdx.x;
    if (gt < KCODES) g_probs[gt] = 0.0f;
    if (gt == 0) g_loss = 0.0f;

    int warp = threadIdx.x >> 5;
    int lane = threadIdx.x & 31;
    int code = blockIdx.x * 8 + warp;   // 128 blocks * 8 warps = 1024 codes
    const float4* wp = (const float4*)(W + (size_t)code * DDIM + lane * 8);
    float4 a = wp[0], b = wp[1];
    float s = a.x*a.x + a.y*a.y + a.z*a.z + a.w*a.w
            + b.x*b.x + b.y*b.y + b.z*b.z + b.w*b.w;
    #pragma unroll
    for (int o = 16; o; o >>= 1) s += __shfl_xor_sync(0xffffffffu, s, o);
    if (lane == 0) g_wnorm[code] = s;
}

// ---------------------------------------------------------------------------
// Main: fused distance-GEMM + per-row top-2 + weights + encodings scatter +
//       quantized rows + loss partial. One block = 128 rows (never crosses
//       a batch: 1024 % 128 == 0).
// Shared memory manual layout (52736 B dynamic):
//   [0      ) wn[1024]      4096
//   [4096   ) xn[128]        512
//   [4608   ) w1[128]        512
//   [5120   ) w2[128]        512
//   [5632   ) i1[128]        512
//   [6144   ) i2[128]        512
//   [6656   ) part[256]     1024
//   [7680   ) Xs[16][128]   8192
//   [15872  ) Ws[16][64]    4096
//   [19968  ) sc[128][32]  16384
//   [36352  ) id[128][32]  16384
// ---------------------------------------------------------------------------
__global__ void __launch_bounds__(NTHREADS, 2)
vq_main(const float* __restrict__ x, const float* __restrict__ W,
        float* __restrict__ out) {
    extern __shared__ char smem[];
    float* sh_wn   = (float*)(smem);
    float* sh_xn   = (float*)(smem + 4096);
    float* sh_w1   = (float*)(smem + 4608);
    float* sh_w2   = (float*)(smem + 5120);
    int*   sh_i1   = (int*)  (smem + 5632);
    int*   sh_i2   = (int*)  (smem + 6144);
    float* sh_part = (float*)(smem + 6656);
    float* Xs      = (float*)(smem + 7680);    // [BK][TM]
    float* Ws      = (float*)(smem + 15872);   // [BK][TN]
    float* sh_sc   = (float*)(smem + 19968);   // [TM][32]
    int*   sh_id   = (int*)  (smem + 36352);   // [TM][32]

    const int t  = threadIdx.x;
    const int tx = t & 15;     // column group
    const int ty = t >> 4;     // row group
    const int row0 = blockIdx.x * TM;
    const int b    = row0 / HWSZ;
    const int hw0  = row0 % HWSZ;
    const float* xblk = x + (size_t)b * DDIM * HWSZ + hw0;  // elem (k,r) at [k*HWSZ+r]

    // ---- stage wnorm, compute per-row xnorm -------------------------------
    for (int i = t; i < KCODES; i += NTHREADS) sh_wn[i] = g_wnorm[i];
    {
        int r = t & 127, half = t >> 7;
        float s = 0.0f;
        int kbeg = half * 128;
        for (int k = kbeg; k < kbeg + 128; ++k) {
            float v = xblk[(size_t)k * HWSZ + r];
            s = fmaf(v, v, s);
        }
        sh_part[t] = s;
    }
    __syncthreads();
    if (t < TM) sh_xn[t] = sh_part[t] + sh_part[t + 128];

    // ---- GEMM with fused running top-2 (score = wnorm - 2*dot) ------------
    float s1[8], s2[8];
    int   i1r[8], i2r[8];
    #pragma unroll
    for (int i = 0; i < 8; i++) { s1[i] = 3.4e38f; s2[i] = 3.4e38f; i1r[i] = 0; i2r[i] = 0; }

    for (int nt = 0; nt < NT; nt++) {
        const int col0 = nt * TN;
        float acc[8][4];
        #pragma unroll
        for (int i = 0; i < 8; i++) {
            #pragma unroll
            for (int j = 0; j < 4; j++) acc[i][j] = 0.0f;
        }

        // prefetch chunk 0 into registers
        const int r4 = (t & 31) * 4;
        const int kl = t >> 5;
        const int wc = t >> 2;
        const int kq = (t & 3) * 4;
        float4 px0, px1, pw;
        px0 = *(const float4*)(xblk + (size_t)(kl    ) * HWSZ + r4);
        px1 = *(const float4*)(xblk + (size_t)(kl + 8) * HWSZ + r4);
        pw  = *(const float4*)(W + (size_t)(col0 + wc) * DDIM + kq);

        for (int kc = 0; kc < DDIM / BK; kc++) {
            // store prefetched chunk to smem
            *(float4*)(Xs + (kl    ) * TM + r4) = px0;
            *(float4*)(Xs + (kl + 8) * TM + r4) = px1;
            Ws[(kq + 0) * TN + wc] = pw.x;
            Ws[(kq + 1) * TN + wc] = pw.y;
            Ws[(kq + 2) * TN + wc] = pw.z;
            Ws[(kq + 3) * TN + wc] = pw.w;
            __syncthreads();

            // issue next chunk's global loads (overlap with compute)
            if (kc + 1 < DDIM / BK) {
                int k0n = (kc + 1) * BK;
                px0 = *(const float4*)(xblk + (size_t)(k0n + kl    ) * HWSZ + r4);
                px1 = *(const float4*)(xblk + (size_t)(k0n + kl + 8) * HWSZ + r4);
                pw  = *(const float4*)(W + (size_t)(col0 + wc) * DDIM + k0n + kq);
            }

            #pragma unroll
            for (int k = 0; k < BK; k++) {
                float4 a0 = *(float4*)(Xs + k * TM + ty * 4);
                float4 a1 = *(float4*)(Xs + k * TM + 64 + ty * 4);
                float4 bb = *(float4*)(Ws + k * TN + tx * 4);
                float av[8] = {a0.x, a0.y, a0.z, a0.w, a1.x, a1.y, a1.z, a1.w};
                float bv[4] = {bb.x, bb.y, bb.z, bb.w};
                #pragma unroll
                for (int i = 0; i < 8; i++) {
                    #pragma unroll
                    for (int j = 0; j < 4; j++)
                        acc[i][j] = fmaf(av[i], bv[j], acc[i][j]);
                }
            }
            __syncthreads();
        }

        // epilogue: fold this column tile into per-thread top-2
        #pragma unroll
        for (int i = 0; i < 8; i++) {
            #pragma unroll
            for (int j = 0; j < 4; j++) {
                int c = col0 + tx * 4 + j;
                float s = sh_wn[c] - 2.0f * acc[i][j];
                if (s < s1[i])      { s2[i] = s1[i]; i2r[i] = i1r[i]; s1[i] = s; i1r[i] = c; }
                else if (s < s2[i]) { s2[i] = s;     i2r[i] = c; }
            }
        }
    }

    // ---- combine top-2 across the 16 column-group threads per row ---------
    __syncthreads();
    #pragma unroll
    for (int i = 0; i < 8; i++) {
        int r = (i < 4) ? (ty * 4 + i) : (64 + ty * 4 + (i - 4));
        sh_sc[r * 32 + tx * 2]     = s1[i];  sh_id[r * 32 + tx * 2]     = i1r[i];
        sh_sc[r * 32 + tx * 2 + 1] = s2[i];  sh_id[r * 32 + tx * 2 + 1] = i2r[i];
    }
    __syncthreads();

    if (t < TM) {
        int r = t;
        float b1 = 3.4e38f, b2 = 3.4e38f; int j1 = 0, j2 = 0;
        #pragma unroll 4
        for (int q = 0; q < 32; q++) {
            float s = sh_sc[r * 32 + q]; int id = sh_id[r * 32 + q];
            if (s < b1)      { b2 = b1; j2 = j1; b1 = s; j1 = id; }
            else if (s < b2) { b2 = s; j2 = id; }
        }
        float xn = sh_xn[r];
        float d1 = b1 + xn, d2 = b2 + xn;
        float inv1 = 1.0f / d1, inv2 = 1.0f / d2;
        float nrm = fmaxf(sqrtf(inv1 * inv1 + inv2 * inv2), 1e-12f);
        float w1 = inv1 / nrm, w2 = inv2 / nrm;
        sh_w1[r] = w1; sh_w2[r] = w2; sh_i1[r] = j1; sh_i2[r] = j2;

        size_t grow = (size_t)(row0 + r);
        float* enc = out + 2 + (size_t)QELEMS;          // encodings base
        enc[grow * KCODES + j1] = w1;
        enc[grow * KCODES + j2] = w2;
        atomicAdd(&g_probs[j1], w1);
        atomicAdd(&g_probs[j2], w2);
    }
    __syncthreads();

    // ---- quantized rows (NCHW) + loss partial -----------------------------
    {
        int r  = t & 127;
        int d0 = (t >> 7) * 128;
        float w1 = sh_w1[r], w2 = sh_w2[r];
        const float* wr1 = W + (size_t)sh_i1[r] * DDIM;
        const float* wr2 = W + (size_t)sh_i2[r] * DDIM;
        const float* xr  = xblk + r;                         // elem d at [d*HWSZ]
        float* qo = out + 1 + (size_t)b * DDIM * HWSZ + hw0 + r;
        float lacc = 0.0f;
        for (int d = d0; d < d0 + 128; d += 4) {
            float4 wa = *(const float4*)(wr1 + d);
            float4 wb = *(const float4*)(wr2 + d);
            float q0 = w1 * wa.x + w2 * wb.x;
            float q1 = w1 * wa.y + w2 * wb.y;
            float q2 = w1 * wa.z + w2 * wb.z;
            float q3 = w1 * wa.w + w2 * wb.w;
            float e;
            e = q0 - xr[(size_t)(d + 0) * HWSZ]; lacc = fmaf(e, e, lacc); qo[(size_t)(d + 0) * HWSZ] = q0;
            e = q1 - xr[(size_t)(d + 1) * HWSZ]; lacc = fmaf(e, e, lacc); qo[(size_t)(d + 1) * HWSZ] = q1;
            e = q2 - xr[(size_t)(d + 2) * HWSZ]; lacc = fmaf(e, e, lacc); qo[(size_t)(d + 2) * HWSZ] = q2;
            e = q3 - xr[(size_t)(d + 3) * HWSZ]; lacc = fmaf(e, e, lacc); qo[(size_t)(d + 3) * HWSZ] = q3;
        }
        #pragma unroll
        for (int o = 16; o; o >>= 1) lacc += __shfl_xor_sync(0xffffffffu, lacc, o);
        __syncthreads();
        if ((t & 31) == 0) sh_part[t >> 5] = lacc;
        __syncthreads();
        if (t == 0) {
            float s = 0.0f;
            #pragma unroll
            for (int w = 0; w < 8; w++) s += sh_part[w];
            atomicAdd(&g_loss, s);
        }
    }
}

// ---------------------------------------------------------------------------
// Finalize: perplexity + loss scalars
// ---------------------------------------------------------------------------
__global__ void vq_final(float* __restrict__ out) {
    __shared__ float red[32];
    int t = threadIdx.x;                    // 1024 threads
    float p = g_probs[t] * (1.0f / 32768.0f);
    float e = -p * logf(p + 1e-10f);
    #pragma unroll
    for (int o = 16; o; o >>= 1) e += __shfl_xor_sync(0xffffffffu, e, o);
    if ((t & 31) == 0) red[t >> 5] = e;
    __syncthreads();
    if (t == 0) {
        float s = 0.0f;
        #pragma unroll
        for (int w = 0; w < 32; w++) s += red[w];
        out[(size_t)QELEMS + 1] = expf(s);                       // perplexity
        out[0] = 1.25f * g_loss / (float)QELEMS;                 // loss
    }
}

// ---------------------------------------------------------------------------
extern "C" void kernel_launch(void* const* d_in, const int* in_sizes, int n_in,
                              void* d_out, int out_size) {
    const float* x = (const float*)d_in[0];   // (32,256,32,32) fp32
    const float* W = (const float*)d_in[1];   // (1024,256) fp32
    float* out = (float*)d_out;
    (void)in_sizes; (void)n_in; (void)out_size;   // n == 2 (fixed)

    cudaFuncSetAttribute(vq_main, cudaFuncAttributeMaxDynamicSharedMemorySize, 53248);

    // zero encodings region (poisoned 0xAA by harness)
    cudaMemsetAsync(out + 2 + (size_t)QELEMS, 0, (size_t)ENC_ELEMS * sizeof(float));
    vq_init<<<128, 256>>>(W);
    vq_main<<<NROWS / TM, NTHREADS, 52736>>>(x, W, out);
    vq_final<<<1, 1024>>>(out);
}

// round 9
// speedup vs baseline: 2.4364x; 2.4364x over previous
#include <cuda_runtime.h>
#include <math.h>
#include <stdint.h>

#define DDIM    256
#define HWSZ    1024
#define NROWS   32768
#define KCODES  1024
#define QELEMS  8388608      // 32*256*32*32
#define TM      128
#define NTILE   64           // codes per B tile
#define NTILES  16
#define NTHREADS 256
#define PITCH   260          // floats per smem row (conflict-free mma frag reads)

// ---- smem layout (bytes) ----
#define OFF_A    0                       // 128 x PITCH fp32      133120
#define OFF_B    133120                  // 64 x PITCH fp32        66560
// aliased into B region after GEMM:
#define OFF_SC   133120                  // sc[128][24] float      12288
#define OFF_CI   145408                  // ci[128][24] int        12288
#define OFF_SW1  157696
#define OFF_SW2  158208
#define OFF_SI1  158720
#define OFF_SI2  159232
#define OFF_WN   199680                  // wnorm[1024]             4096
#define OFF_XN   203776                  // xnorm[128]               512
#define OFF_PART 204288                  // reduce scratch[256]     1024
#define SMEM_BYTES 205312

#define DELTA 0.25f          // tf32-score refine threshold

__device__ float g_wnorm[KCODES];
__device__ float g_probs[KCODES];
__device__ float g_loss;

// ---------------------------------------------------------------------------
__device__ __forceinline__ void mma_tf32(float* d, const uint32_t* a, const uint32_t* b) {
    asm volatile(
        "mma.sync.aligned.m16n8k8.row.col.f32.tf32.tf32.f32 "
        "{%0,%1,%2,%3}, {%4,%5,%6,%7}, {%8,%9}, {%0,%1,%2,%3};"
        : "+f"(d[0]), "+f"(d[1]), "+f"(d[2]), "+f"(d[3])
        : "r"(a[0]), "r"(a[1]), "r"(a[2]), "r"(a[3]), "r"(b[0]), "r"(b[1]));
}

// ---------------------------------------------------------------------------
// Init: zero accumulators, wnorm per code (one warp per code)
// ---------------------------------------------------------------------------
__global__ void vq_init(const float* __restrict__ W) {
    int gt = blockIdx.x * 256 + threadIdx.x;
    if (gt < KCODES) g_probs[gt] = 0.0f;
    if (gt == 0) g_loss = 0.0f;
    int warp = threadIdx.x >> 5, lane = threadIdx.x & 31;
    int code = blockIdx.x * 8 + warp;
    const float4* wp = (const float4*)(W + (size_t)code * DDIM + lane * 8);
    float4 a = wp[0], b = wp[1];
    float s = a.x*a.x + a.y*a.y + a.z*a.z + a.w*a.w
            + b.x*b.x + b.y*b.y + b.z*b.z + b.w*b.w;
    #pragma unroll
    for (int o = 16; o; o >>= 1) s += __shfl_xor_sync(0xffffffffu, s, o);
    if (lane == 0) g_wnorm[code] = s;
}

// ---------------------------------------------------------------------------
// Main fused kernel: tf32 mma GEMM -> per-owner top-3 -> exact refine ->
// weights/encodings/probs -> quantized + loss
// ---------------------------------------------------------------------------
__global__ void __launch_bounds__(NTHREADS, 1)
vq_main(const float* __restrict__ x, const float* __restrict__ W,
        float* __restrict__ out) {
    extern __shared__ __align__(16) char smem[];
    float* As   = (float*)(smem + OFF_A);
    float* Bs   = (float*)(smem + OFF_B);
    float* sc   = (float*)(smem + OFF_SC);
    int*   ci   = (int*)  (smem + OFF_CI);
    float* sw1  = (float*)(smem + OFF_SW1);
    float* sw2  = (float*)(smem + OFF_SW2);
    int*   si1  = (int*)  (smem + OFF_SI1);
    int*   si2  = (int*)  (smem + OFF_SI2);
    float* wn   = (float*)(smem + OFF_WN);
    float* xn   = (float*)(smem + OFF_XN);
    float* part = (float*)(smem + OFF_PART);

    const int t    = threadIdx.x;
    const int lane = t & 31;
    const int warp = t >> 5;
    const int g    = lane >> 2;          // group id (0..7)
    const int tg   = lane & 3;           // thread-in-group (0..3)
    const int wm   = warp & 3;           // M warp (rows wm*32..+31)
    const int wnb  = (warp >> 2) * 32;   // N warp base within 64-wide tile

    const int row0 = blockIdx.x * TM;
    const int bb   = row0 / HWSZ;
    const int hw0  = row0 % HWSZ;
    const float* xblk = x + (size_t)bb * DDIM * HWSZ + hw0;   // elem (d,r): [d*HWSZ+r]
    float* enc = out + 2 + (size_t)QELEMS;

    // stage wnorm
    for (int i = t; i < KCODES; i += NTHREADS) wn[i] = g_wnorm[i];

    // zero this CTA's encodings rows (enc base is only 8B-aligned: use float2!)
    {
        float2 z = make_float2(0.f, 0.f);
        float2* e2 = (float2*)(enc + (size_t)row0 * KCODES);
        #pragma unroll 8
        for (int i = 0; i < 256; i++) e2[t + i * 256] = z;
    }

    // load A (x rows) into smem [r][d] (pitch 260), accumulate xnorm partials
    {
        int r = t & 127;
        float acc = 0.0f;
        #pragma unroll 4
        for (int i = 0; i < 128; i++) {
            int d = (t >> 7) + i * 2;
            float v = __ldg(xblk + (size_t)d * HWSZ + r);
            acc = fmaf(v, v, acc);
            As[r * PITCH + d] = v;
        }
        part[t] = acc;
    }
    __syncthreads();
    if (t < TM) xn[t] = part[t] + part[t + 128];

    // ---- GEMM over 16 column tiles with fused per-owner top-3 ------------
    float ts[4][3]; int ti[4][3];
    #pragma unroll
    for (int s = 0; s < 4; s++)
        #pragma unroll
        for (int q = 0; q < 3; q++) { ts[s][q] = 3.4e38f; ti[s][q] = 0; }

    for (int nt = 0; nt < NTILES; nt++) {
        const int n0 = nt * NTILE;
        __syncthreads();   // previous tile's consumers done
        // load B tile: 64 codes x 256 floats
        #pragma unroll
        for (int i = 0; i < 16; i++) {
            int idx = t + i * 256;
            int n = idx >> 6;
            int kq = (idx & 63) << 2;
            float4 v = __ldg((const float4*)(W + (size_t)(n0 + n) * DDIM + kq));
            *(float4*)(Bs + n * PITCH + kq) = v;
        }
        __syncthreads();

        float acc[2][4][4];
        #pragma unroll
        for (int mi = 0; mi < 2; mi++)
            #pragma unroll
            for (int ni = 0; ni < 4; ni++)
                #pragma unroll
                for (int q = 0; q < 4; q++) acc[mi][ni][q] = 0.0f;

        #pragma unroll 4
        for (int kc = 0; kc < 32; kc++) {
            const int k0 = kc * 8;
            uint32_t a[2][4], b[4][2];
            #pragma unroll
            for (int mi = 0; mi < 2; mi++) {
                const int r = wm * 32 + mi * 16 + g;
                a[mi][0] = __float_as_uint(As[r * PITCH + k0 + tg]);
                a[mi][1] = __float_as_uint(As[(r + 8) * PITCH + k0 + tg]);
                a[mi][2] = __float_as_uint(As[r * PITCH + k0 + tg + 4]);
                a[mi][3] = __float_as_uint(As[(r + 8) * PITCH + k0 + tg + 4]);
            }
            #pragma unroll
            for (int ni = 0; ni < 4; ni++) {
                const int n = wnb + ni * 8 + g;
                b[ni][0] = __float_as_uint(Bs[n * PITCH + k0 + tg]);
                b[ni][1] = __float_as_uint(Bs[n * PITCH + k0 + tg + 4]);
            }
            #pragma unroll
            for (int mi = 0; mi < 2; mi++)
                #pragma unroll
                for (int ni = 0; ni < 4; ni++)
                    mma_tf32(acc[mi][ni], a[mi], b[ni]);
        }

        // fold scores into per-owner top-3 (slot = mi*2 + half)
        #pragma unroll
        for (int mi = 0; mi < 2; mi++) {
            #pragma unroll
            for (int half = 0; half < 2; half++) {
                const int s = mi * 2 + half;
                #pragma unroll
                for (int ni = 0; ni < 4; ni++) {
                    #pragma unroll
                    for (int j = 0; j < 2; j++) {
                        const int c = n0 + wnb + ni * 8 + 2 * tg + j;
                        float v = wn[c] - 2.0f * acc[mi][ni][half * 2 + j];
                        if (v < ts[s][2]) {
                            ts[s][2] = v; ti[s][2] = c;
                            if (ts[s][2] < ts[s][1]) {
                                float f = ts[s][1]; ts[s][1] = ts[s][2]; ts[s][2] = f;
                                int  ii = ti[s][1]; ti[s][1] = ti[s][2]; ti[s][2] = ii;
                            }
                            if (ts[s][1] < ts[s][0]) {
                                float f = ts[s][0]; ts[s][0] = ts[s][1]; ts[s][1] = f;
                                int  ii = ti[s][0]; ti[s][0] = ti[s][1]; ti[s][1] = ii;
                            }
                        }
                    }
                }
            }
        }
    }
    __syncthreads();   // B region free -> write candidates (aliased)

    {
        const int o = (warp >> 2) * 4 + tg;   // owner 0..7
        #pragma unroll
        for (int mi = 0; mi < 2; mi++)
            #pragma unroll
            for (int half = 0; half < 2; half++) {
                const int s = mi * 2 + half;
                const int r = wm * 32 + mi * 16 + half * 8 + g;
                #pragma unroll
                for (int q = 0; q < 3; q++) {
                    sc[r * 24 + o * 3 + q] = ts[s][q];
                    ci[r * 24 + o * 3 + q] = ti[s][q];
                }
            }
    }
    __syncthreads();

    // ---- thresholded exact fp32 refine (thread-per-row) ------------------
    if (t < TM) {
        const int r = t;
        const float xnr = xn[r];
        // 2nd smallest tf32 score among 24
        float m1 = 3.4e38f, m2 = 3.4e38f;
        #pragma unroll 8
        for (int q = 0; q < 24; q++) {
            float s = sc[r * 24 + q];
            if (s < m1) { m2 = m1; m1 = s; } else if (s < m2) m2 = s;
        }
        const float thr = m2 + DELTA;
        float b1 = 3.4e38f, b2 = 3.4e38f; int j1 = 0, j2 = 0;
        for (int q = 0; q < 24; q++) {
            if (sc[r * 24 + q] > thr) continue;
            const int c = ci[r * 24 + q];
            const float4* wp = (const float4*)(W + (size_t)c * DDIM);
            const float4* ap = (const float4*)(As + r * PITCH);
            float p = 0.0f;
            #pragma unroll 8
            for (int i = 0; i < 64; i++) {
                float4 wv = __ldg(wp + i);
                float4 av = ap[i];
                p = fmaf(av.x, wv.x, p); p = fmaf(av.y, wv.y, p);
                p = fmaf(av.z, wv.z, p); p = fmaf(av.w, wv.w, p);
            }
            float dist = xnr + wn[c] - 2.0f * p;
            if (dist < b1)      { b2 = b1; j2 = j1; b1 = dist; j1 = c; }
            else if (dist < b2) { b2 = dist; j2 = c; }
        }
        float inv1 = 1.0f / b1, inv2 = 1.0f / b2;
        float nrm = fmaxf(sqrtf(fmaf(inv1, inv1, inv2 * inv2)), 1e-12f);
        float w1o = inv1 / nrm, w2o = inv2 / nrm;
        sw1[r] = w1o; sw2[r] = w2o; si1[r] = j1; si2[r] = j2;
        size_t grow = (size_t)(row0 + r);
        enc[grow * KCODES + j1] = w1o;
        enc[grow * KCODES + j2] = w2o;
        atomicAdd(&g_probs[j1], w1o);
        atomicAdd(&g_probs[j2], w2o);
    }
    __syncthreads();

    // ---- quantized rows (NCHW) + loss partial ----------------------------
    {
        const int r  = t & 127;
        const int d0 = (t >> 7) * 128;
        const float w1o = sw1[r], w2o = sw2[r];
        const float* wr1 = W + (size_t)si1[r] * DDIM;
        const float* wr2 = W + (size_t)si2[r] * DDIM;
        float* qo = out + 1 + (size_t)bb * DDIM * HWSZ + hw0 + r;
        float lacc = 0.0f;
        for (int d = d0; d < d0 + 128; d += 4) {
            float4 wa = __ldg((const float4*)(wr1 + d));
            float4 wb = __ldg((const float4*)(wr2 + d));
            float4 av = *(const float4*)(As + r * PITCH + d);
            float q0 = fmaf(w1o, wa.x, w2o * wb.x);
            float q1 = fmaf(w1o, wa.y, w2o * wb.y);
            float q2 = fmaf(w1o, wa.z, w2o * wb.z);
            float q3 = fmaf(w1o, wa.w, w2o * wb.w);
            float e;
            e = q0 - av.x; lacc = fmaf(e, e, lacc); qo[(size_t)(d + 0) * HWSZ] = q0;
            e = q1 - av.y; lacc = fmaf(e, e, lacc); qo[(size_t)(d + 1) * HWSZ] = q1;
            e = q2 - av.z; lacc = fmaf(e, e, lacc); qo[(size_t)(d + 2) * HWSZ] = q2;
            e = q3 - av.w; lacc = fmaf(e, e, lacc); qo[(size_t)(d + 3) * HWSZ] = q3;
        }
        #pragma unroll
        for (int o = 16; o; o >>= 1) lacc += __shfl_xor_sync(0xffffffffu, lacc, o);
        __syncthreads();
        if ((t & 31) == 0) part[t >> 5] = lacc;
        __syncthreads();
        if (t == 0) {
            float s = 0.0f;
            #pragma unroll
            for (int w = 0; w < 8; w++) s += part[w];
            atomicAdd(&g_loss, s);
        }
    }
}

// ---------------------------------------------------------------------------
// Finalize: perplexity + loss scalars
// ---------------------------------------------------------------------------
__global__ void vq_final(float* __restrict__ out) {
    __shared__ float red[32];
    int t = threadIdx.x;                 // 1024 threads
    float p = g_probs[t] * (1.0f / 32768.0f);
    float e = -p * logf(p + 1e-10f);
    #pragma unroll
    for (int o = 16; o; o >>= 1) e += __shfl_xor_sync(0xffffffffu, e, o);
    if ((t & 31) == 0) red[t >> 5] = e;
    __syncthreads();
    if (t == 0) {
        float s = 0.0f;
        #pragma unroll
        for (int w = 0; w < 32; w++) s += red[w];
        out[(size_t)QELEMS + 1] = expf(s);              // perplexity
        out[0] = 1.25f * g_loss / (float)QELEMS;        // loss
    }
}

// ---------------------------------------------------------------------------
extern "C" void kernel_launch(void* const* d_in, const int* in_sizes, int n_in,
                              void* d_out, int out_size) {
    const float* x = (const float*)d_in[0];   // (32,256,32,32) fp32
    const float* W = (const float*)d_in[1];   // (1024,256) fp32
    float* out = (float*)d_out;
    (void)in_sizes; (void)n_in; (void)out_size;

    cudaFuncSetAttribute(vq_main, cudaFuncAttributeMaxDynamicSharedMemorySize, SMEM_BYTES);
    vq_init<<<128, 256>>>(W);
    vq_main<<<NROWS / TM, NTHREADS, SMEM_BYTES>>>(x, W, out);
    vq_final<<<1, 1024>>>(out);
}

// round 10
// speedup vs baseline: 2.9183x; 1.1978x over previous
#include <cuda_runtime.h>
#include <cuda_fp16.h>
#include <math.h>
#include <stdint.h>

#define DDIM    256
#define HWSZ    1024
#define NROWS   32768
#define KCODES  1024
#define QELEMS  8388608      // 32*256*32*32
#define TM      128
#define NTILE   64           // codes per B tile
#define NTILES  16
#define KC16    16           // 256 / 16 (fp16 K=16 per MMA)
#define NTHREADS 256
#define PITCH   260          // fp32 A floats per smem row
#define BP      264          // fp16 B halfs per smem row (132 words: conflict-free)

// ---- smem layout (bytes) ----
#define OFF_A    0                       // 128 x PITCH fp32      133120
#define OFF_B16  133120                  // 64 x BP fp16           33792
// aliased into B16 region after GEMM:
#define OFF_SC   133120                  // sc[128][24] float      12288
#define OFF_CI   145408                  // ci[128][24] int        12288
#define OFF_SW1  157696
#define OFF_SW2  158208
#define OFF_SI1  158720
#define OFF_SI2  159232
#define OFF_WN   166912                  // wnorm[1024]             4096
#define OFF_XN   171008                  // xnorm[128]               512
#define OFF_PART 171520                  // reduce scratch[256]     1024
#define SMEM_BYTES 172544

#define DELTA 0.25f          // approx-score refine threshold

__device__ float g_wnorm[KCODES];
__device__ float g_probs[KCODES];
__device__ float g_loss;

// ---------------------------------------------------------------------------
__device__ __forceinline__ void mma_f16(float* d, const uint32_t* a,
                                        uint32_t b0, uint32_t b1) {
    asm volatile(
        "mma.sync.aligned.m16n8k16.row.col.f32.f16.f16.f32 "
        "{%0,%1,%2,%3}, {%4,%5,%6,%7}, {%8,%9}, {%0,%1,%2,%3};"
        : "+f"(d[0]), "+f"(d[1]), "+f"(d[2]), "+f"(d[3])
        : "r"(a[0]), "r"(a[1]), "r"(a[2]), "r"(a[3]), "r"(b0), "r"(b1));
}
__device__ __forceinline__ uint32_t pack_h2(float lo, float hi) {
    __half2 h = __floats2half2_rn(lo, hi);   // lo -> .x (low 16 bits)
    return *reinterpret_cast<uint32_t*>(&h);
}

// ---------------------------------------------------------------------------
// Init: zero accumulators, wnorm per code (one warp per code)
// ---------------------------------------------------------------------------
__global__ void vq_init(const float* __restrict__ W) {
    int gt = blockIdx.x * 256 + threadIdx.x;
    if (gt < KCODES) g_probs[gt] = 0.0f;
    if (gt == 0) g_loss = 0.0f;
    int warp = threadIdx.x >> 5, lane = threadIdx.x & 31;
    int code = blockIdx.x * 8 + warp;
    const float4* wp = (const float4*)(W + (size_t)code * DDIM + lane * 8);
    float4 a = wp[0], b = wp[1];
    float s = a.x*a.x + a.y*a.y + a.z*a.z + a.w*a.w
            + b.x*b.x + b.y*b.y + b.z*b.z + b.w*b.w;
    #pragma unroll
    for (int o = 16; o; o >>= 1) s += __shfl_xor_sync(0xffffffffu, s, o);
    if (lane == 0) g_wnorm[code] = s;
}

// ---------------------------------------------------------------------------
// Main fused kernel: fp16 mma GEMM (A frags in regs) -> per-owner top-3 ->
// exact fp32 refine -> weights/encodings/probs -> quantized + loss
// ---------------------------------------------------------------------------
__global__ void __launch_bounds__(NTHREADS, 1)
vq_main(const float* __restrict__ x, const float* __restrict__ W,
        float* __restrict__ out) {
    extern __shared__ __align__(16) char smem[];
    float*  As   = (float*)(smem + OFF_A);
    __half* Bs16 = (__half*)(smem + OFF_B16);
    float*  sc   = (float*)(smem + OFF_SC);
    int*    ci   = (int*)  (smem + OFF_CI);
    float*  sw1  = (float*)(smem + OFF_SW1);
    float*  sw2  = (float*)(smem + OFF_SW2);
    int*    si1  = (int*)  (smem + OFF_SI1);
    int*    si2  = (int*)  (smem + OFF_SI2);
    float*  wn   = (float*)(smem + OFF_WN);
    float*  xn   = (float*)(smem + OFF_XN);
    float*  part = (float*)(smem + OFF_PART);

    const int t    = threadIdx.x;
    const int lane = t & 31;
    const int warp = t >> 5;
    const int g    = lane >> 2;          // group id (0..7)
    const int tg   = lane & 3;           // thread-in-group (0..3)
    const int wm   = warp & 3;           // M warp (rows wm*32..+31)
    const int wnb  = (warp >> 2) * 32;   // N warp base within 64-wide tile

    const int row0 = blockIdx.x * TM;
    const int bb   = row0 / HWSZ;
    const int hw0  = row0 % HWSZ;
    const float* xblk = x + (size_t)bb * DDIM * HWSZ + hw0;   // elem (d,r): [d*HWSZ+r]
    float* enc = out + 2 + (size_t)QELEMS;

    // stage wnorm
    for (int i = t; i < KCODES; i += NTHREADS) wn[i] = g_wnorm[i];

    // zero this CTA's encodings rows (enc base is only 8B-aligned: float2)
    {
        float2 z = make_float2(0.f, 0.f);
        float2* e2 = (float2*)(enc + (size_t)row0 * KCODES);
        #pragma unroll 8
        for (int i = 0; i < 256; i++) e2[t + i * 256] = z;
    }

    // load A (x rows) into smem [r][d] (pitch 260), accumulate xnorm partials
    {
        int r = t & 127;
        float acc = 0.0f;
        #pragma unroll 4
        for (int i = 0; i < 128; i++) {
            int d = (t >> 7) + i * 2;
            float v = __ldg(xblk + (size_t)d * HWSZ + r);
            acc = fmaf(v, v, acc);
            As[r * PITCH + d] = v;
        }
        part[t] = acc;
    }
    __syncthreads();
    if (t < TM) xn[t] = part[t] + part[t + 128];

    // ---- preload ALL A fragments (fp16) into registers: 16 kc x 8 regs ---
    uint32_t afr[KC16][8];
    {
        const int r0 = wm * 32 + g;      // mi=0 row; mi=1 adds 16
        #pragma unroll
        for (int kc = 0; kc < KC16; kc++) {
            const int k0 = kc * 16 + 2 * tg;
            #pragma unroll
            for (int mi = 0; mi < 2; mi++) {
                const float* base = As + (r0 + mi * 16) * PITCH + k0;
                float2 v0 = *(const float2*)(base);
                float2 v1 = *(const float2*)(base + 8 * PITCH);
                float2 v2 = *(const float2*)(base + 8);
                float2 v3 = *(const float2*)(base + 8 * PITCH + 8);
                afr[kc][mi * 4 + 0] = pack_h2(v0.x, v0.y);
                afr[kc][mi * 4 + 1] = pack_h2(v1.x, v1.y);
                afr[kc][mi * 4 + 2] = pack_h2(v2.x, v2.y);
                afr[kc][mi * 4 + 3] = pack_h2(v3.x, v3.y);
            }
        }
    }

    // ---- GEMM over 16 column tiles with fused per-owner top-3 ------------
    float ts[4][3]; int ti[4][3];
    #pragma unroll
    for (int s = 0; s < 4; s++)
        #pragma unroll
        for (int q = 0; q < 3; q++) { ts[s][q] = 3.4e38f; ti[s][q] = 0; }

    for (int nt = 0; nt < NTILES; nt++) {
        const int n0 = nt * NTILE;
        __syncthreads();   // previous tile's consumers done
        // load B tile: 64 codes x 256 floats -> fp16 smem
        #pragma unroll
        for (int i = 0; i < 16; i++) {
            int idx = t + i * 256;         // float4 units
            int n = idx >> 6;
            int kq = (idx & 63) << 2;
            float4 v = __ldg((const float4*)(W + (size_t)(n0 + n) * DDIM + kq));
            uint2 h;
            h.x = pack_h2(v.x, v.y);
            h.y = pack_h2(v.z, v.w);
            *(uint2*)(Bs16 + n * BP + kq) = h;
        }
        __syncthreads();

        float acc[2][4][4];
        #pragma unroll
        for (int mi = 0; mi < 2; mi++)
            #pragma unroll
            for (int ni = 0; ni < 4; ni++)
                #pragma unroll
                for (int q = 0; q < 4; q++) acc[mi][ni][q] = 0.0f;

        #pragma unroll
        for (int kc = 0; kc < KC16; kc++) {
            const int k0 = kc * 16;
            uint32_t b[4][2];
            #pragma unroll
            for (int ni = 0; ni < 4; ni++) {
                const __half* bp = Bs16 + (wnb + ni * 8 + g) * BP + k0 + 2 * tg;
                b[ni][0] = *(const uint32_t*)(bp);        // k = 2tg, 2tg+1
                b[ni][1] = *(const uint32_t*)(bp + 8);    // k = 2tg+8, 2tg+9
            }
            #pragma unroll
            for (int mi = 0; mi < 2; mi++)
                #pragma unroll
                for (int ni = 0; ni < 4; ni++)
                    mma_f16(acc[mi][ni], &afr[kc][mi * 4], b[ni][0], b[ni][1]);
        }

        // fold scores into per-owner top-3 (slot = mi*2 + half)
        #pragma unroll
        for (int mi = 0; mi < 2; mi++) {
            #pragma unroll
            for (int half = 0; half < 2; half++) {
                const int s = mi * 2 + half;
                #pragma unroll
                for (int ni = 0; ni < 4; ni++) {
                    #pragma unroll
                    for (int j = 0; j < 2; j++) {
                        const int c = n0 + wnb + ni * 8 + 2 * tg + j;
                        float v = wn[c] - 2.0f * acc[mi][ni][half * 2 + j];
                        if (v < ts[s][2]) {
                            ts[s][2] = v; ti[s][2] = c;
                            if (ts[s][2] < ts[s][1]) {
                                float f = ts[s][1]; ts[s][1] = ts[s][2]; ts[s][2] = f;
                                int  ii = ti[s][1]; ti[s][1] = ti[s][2]; ti[s][2] = ii;
                            }
                            if (ts[s][1] < ts[s][0]) {
                                float f = ts[s][0]; ts[s][0] = ts[s][1]; ts[s][1] = f;
                                int  ii = ti[s][0]; ti[s][0] = ti[s][1]; ti[s][1] = ii;
                            }
                        }
                    }
                }
            }
        }
    }
    __syncthreads();   // B16 region free -> write candidates (aliased)

    {
        const int o = (warp >> 2) * 4 + tg;   // owner 0..7
        #pragma unroll
        for (int mi = 0; mi < 2; mi++)
            #pragma unroll
            for (int half = 0; half < 2; half++) {
                const int s = mi * 2 + half;
                const int r = wm * 32 + mi * 16 + half * 8 + g;
                #pragma unroll
                for (int q = 0; q < 3; q++) {
                    sc[r * 24 + o * 3 + q] = ts[s][q];
                    ci[r * 24 + o * 3 + q] = ti[s][q];
                }
            }
    }
    __syncthreads();

    // ---- thresholded exact fp32 refine (thread-per-row) ------------------
    if (t < TM) {
        const int r = t;
        const float xnr = xn[r];
        // 2nd smallest approx score among 24
        float m1 = 3.4e38f, m2 = 3.4e38f;
        #pragma unroll 8
        for (int q = 0; q < 24; q++) {
            float s = sc[r * 24 + q];
            if (s < m1) { m2 = m1; m1 = s; } else if (s < m2) m2 = s;
        }
        const float thr = m2 + DELTA;
        float b1 = 3.4e38f, b2 = 3.4e38f; int j1 = 0, j2 = 0;
        for (int q = 0; q < 24; q++) {
            if (sc[r * 24 + q] > thr) continue;
            const int c = ci[r * 24 + q];
            const float4* wp = (const float4*)(W + (size_t)c * DDIM);
            const float4* ap = (const float4*)(As + r * PITCH);
            float p = 0.0f;
            #pragma unroll 8
            for (int i = 0; i < 64; i++) {
                float4 wv = __ldg(wp + i);
                float4 av = ap[i];
                p = fmaf(av.x, wv.x, p); p = fmaf(av.y, wv.y, p);
                p = fmaf(av.z, wv.z, p); p = fmaf(av.w, wv.w, p);
            }
            float dist = xnr + wn[c] - 2.0f * p;
            if (dist < b1)      { b2 = b1; j2 = j1; b1 = dist; j1 = c; }
            else if (dist < b2) { b2 = dist; j2 = c; }
        }
        float inv1 = 1.0f / b1, inv2 = 1.0f / b2;
        float nrm = fmaxf(sqrtf(fmaf(inv1, inv1, inv2 * inv2)), 1e-12f);
        float w1o = inv1 / nrm, w2o = inv2 / nrm;
        sw1[r] = w1o; sw2[r] = w2o; si1[r] = j1; si2[r] = j2;
        size_t grow = (size_t)(row0 + r);
        enc[grow * KCODES + j1] = w1o;
        enc[grow * KCODES + j2] = w2o;
        atomicAdd(&g_probs[j1], w1o);
        atomicAdd(&g_probs[j2], w2o);
    }
    __syncthreads();

    // ---- quantized rows (NCHW) + loss partial ----------------------------
    {
        const int r  = t & 127;
        const int d0 = (t >> 7) * 128;
        const float w1o = sw1[r], w2o = sw2[r];
        const float* wr1 = W + (size_t)si1[r] * DDIM;
        const float* wr2 = W + (size_t)si2[r] * DDIM;
        float* qo = out + 1 + (size_t)bb * DDIM * HWSZ + hw0 + r;
        float lacc = 0.0f;
        for (int d = d0; d < d0 + 128; d += 4) {
            float4 wa = __ldg((const float4*)(wr1 + d));
            float4 wb = __ldg((const float4*)(wr2 + d));
            float4 av = *(const float4*)(As + r * PITCH + d);
            float q0 = fmaf(w1o, wa.x, w2o * wb.x);
            float q1 = fmaf(w1o, wa.y, w2o * wb.y);
            float q2 = fmaf(w1o, wa.z, w2o * wb.z);
            float q3 = fmaf(w1o, wa.w, w2o * wb.w);
            float e;
            e = q0 - av.x; lacc = fmaf(e, e, lacc); qo[(size_t)(d + 0) * HWSZ] = q0;
            e = q1 - av.y; lacc = fmaf(e, e, lacc); qo[(size_t)(d + 1) * HWSZ] = q1;
            e = q2 - av.z; lacc = fmaf(e, e, lacc); qo[(size_t)(d + 2) * HWSZ] = q2;
            e = q3 - av.w; lacc = fmaf(e, e, lacc); qo[(size_t)(d + 3) * HWSZ] = q3;
        }
        #pragma unroll
        for (int o = 16; o; o >>= 1) lacc += __shfl_xor_sync(0xffffffffu, lacc, o);
        __syncthreads();
        if ((t & 31) == 0) part[t >> 5] = lacc;
        __syncthreads();
        if (t == 0) {
            float s = 0.0f;
            #pragma unroll
            for (int w = 0; w < 8; w++) s += part[w];
            atomicAdd(&g_loss, s);
        }
    }
}

// ---------------------------------------------------------------------------
// Finalize: perplexity + loss scalars
// ---------------------------------------------------------------------------
__global__ void vq_final(float* __restrict__ out) {
    __shared__ float red[32];
    int t = threadIdx.x;                 // 1024 threads
    float p = g_probs[t] * (1.0f / 32768.0f);
    float e = -p * logf(p + 1e-10f);
    #pragma unroll
    for (int o = 16; o; o >>= 1) e += __shfl_xor_sync(0xffffffffu, e, o);
    if ((t & 31) == 0) red[t >> 5] = e;
    __syncthreads();
    if (t == 0) {
        float s = 0.0f;
        #pragma unroll
        for (int w = 0; w < 32; w++) s += red[w];
        out[(size_t)QELEMS + 1] = expf(s);              // perplexity
        out[0] = 1.25f * g_loss / (float)QELEMS;        // loss
    }
}

// ---------------------------------------------------------------------------
extern "C" void kernel_launch(void* const* d_in, const int* in_sizes, int n_in,
                              void* d_out, int out_size) {
    const float* x = (const float*)d_in[0];   // (32,256,32,32) fp32
    const float* W = (const float*)d_in[1];   // (1024,256) fp32
    float* out = (float*)d_out;
    (void)in_sizes; (void)n_in; (void)out_size;

    cudaFuncSetAttribute(vq_main, cudaFuncAttributeMaxDynamicSharedMemorySize, SMEM_BYTES);
    vq_init<<<128, 256>>>(W);
    vq_main<<<NROWS / TM, NTHREADS, SMEM_BYTES>>>(x, W, out);
    vq_final<<<1, 1024>>>(out);
}

// round 12
// speedup vs baseline: 3.2204x; 1.1035x over previous
#include <cuda_runtime.h>
#include <cuda_fp16.h>
#include <math.h>
#include <stdint.h>

#define DDIM    256
#define HWSZ    1024
#define NROWS   32768
#define KCODES  1024
#define QELEMS  8388608      // 32*256*32*32
#define TM      64
#define NTILE   64           // codes per B tile
#define NTILES  16
#define KC16    16           // 256 / 16 (fp16 K=16 per MMA)
#define NTHREADS 256
#define PITCH   260          // fp32 A floats per smem row
#define BP      264          // fp16 B halfs per smem row (132 words: conflict-free)

// ---- smem layout (bytes) ----
#define OFF_A    0                       // 64 x PITCH fp32        66560
#define OFF_B16  66560                   // 64 x BP fp16           33792
// aliased into B16 region after GEMM:
#define OFF_SC   66560                   // sc[64][24] float        6144
#define OFF_CI   72704                   // ci[64][24] int          6144
#define OFF_WN   100352                  // wnorm[1024]             4096
#define OFF_XN   104448                  // xnorm[64]                256
#define OFF_PART 104704                  // reduce scratch[256]     1024
#define OFF_SW1  105728
#define OFF_SW2  105984
#define OFF_SI1  106240
#define OFF_SI2  106496
#define SMEM_BYTES 106752

#define DELTA 0.25f          // approx-score refine threshold

__device__ float g_wnorm[KCODES];
__device__ float g_probs[KCODES];
__device__ float g_loss;

// ---------------------------------------------------------------------------
__device__ __forceinline__ void mma_f16(float* d, const uint32_t* a,
                                        uint32_t b0, uint32_t b1) {
    asm volatile(
        "mma.sync.aligned.m16n8k16.row.col.f32.f16.f16.f32 "
        "{%0,%1,%2,%3}, {%4,%5,%6,%7}, {%8,%9}, {%0,%1,%2,%3};"
        : "+f"(d[0]), "+f"(d[1]), "+f"(d[2]), "+f"(d[3])
        : "r"(a[0]), "r"(a[1]), "r"(a[2]), "r"(a[3]), "r"(b0), "r"(b1));
}
__device__ __forceinline__ uint32_t pack_h2(float lo, float hi) {
    __half2 h = __floats2half2_rn(lo, hi);   // lo -> .x (low 16 bits)
    return *reinterpret_cast<uint32_t*>(&h);
}

// ---------------------------------------------------------------------------
// Init: zero accumulators, wnorm per code (one warp per code)
// ---------------------------------------------------------------------------
__global__ void vq_init(const float* __restrict__ W) {
    int gt = blockIdx.x * 256 + threadIdx.x;
    if (gt < KCODES) g_probs[gt] = 0.0f;
    if (gt == 0) g_loss = 0.0f;
    int warp = threadIdx.x >> 5, lane = threadIdx.x & 31;
    int code = blockIdx.x * 8 + warp;
    const float4* wp = (const float4*)(W + (size_t)code * DDIM + lane * 8);
    float4 a = wp[0], b = wp[1];
    float s = a.x*a.x + a.y*a.y + a.z*a.z + a.w*a.w
            + b.x*b.x + b.y*b.y + b.z*b.z + b.w*b.w;
    #pragma unroll
    for (int o = 16; o; o >>= 1) s += __shfl_xor_sync(0xffffffffu, s, o);
    if (lane == 0) g_wnorm[code] = s;
}

// ---------------------------------------------------------------------------
// Main fused kernel (TM=64, 2 CTAs/SM): fp16 mma GEMM (A frags in regs) ->
// per-owner top-3 -> exact fp32 refine -> enc/probs -> quantized + loss
// ---------------------------------------------------------------------------
__global__ void __launch_bounds__(NTHREADS, 2)
vq_main(const float* __restrict__ x, const float* __restrict__ W,
        float* __restrict__ out) {
    extern __shared__ __align__(16) char smem[];
    float*  As   = (float*)(smem + OFF_A);
    __half* Bs16 = (__half*)(smem + OFF_B16);
    float*  sc   = (float*)(smem + OFF_SC);
    int*    ci   = (int*)  (smem + OFF_CI);
    float*  wn   = (float*)(smem + OFF_WN);
    float*  xn   = (float*)(smem + OFF_XN);
    float*  part = (float*)(smem + OFF_PART);
    float*  sw1  = (float*)(smem + OFF_SW1);
    float*  sw2  = (float*)(smem + OFF_SW2);
    int*    si1  = (int*)  (smem + OFF_SI1);
    int*    si2  = (int*)  (smem + OFF_SI2);

    const int t    = threadIdx.x;
    const int lane = t & 31;
    const int warp = t >> 5;
    const int g    = lane >> 2;          // group id (0..7)
    const int tg   = lane & 3;           // thread-in-group (0..3)
    const int wm   = warp & 3;           // M warp: rows wm*16 .. +15
    const int ng   = warp >> 2;          // N group (0..1)
    const int wnb  = ng * 32;            // N base within 64-wide tile

    const int row0 = blockIdx.x * TM;
    const int bb   = row0 / HWSZ;
    const int hw0  = row0 % HWSZ;
    const float* xblk = x + (size_t)bb * DDIM * HWSZ + hw0;   // elem (d,r): [d*HWSZ+r]
    float* enc = out + 2 + (size_t)QELEMS;

    // stage wnorm
    for (int i = t; i < KCODES; i += NTHREADS) wn[i] = g_wnorm[i];

    // zero this CTA's encodings rows (enc base only 8B-aligned: float2)
    {
        float2 z = make_float2(0.f, 0.f);
        float2* e2 = (float2*)(enc + (size_t)row0 * KCODES);
        #pragma unroll 8
        for (int i = 0; i < 128; i++) e2[t + i * 256] = z;
    }

    // load A (x rows) into smem [r][d] (pitch 260), accumulate xnorm partials
    {
        int r = t & 63;
        float acc = 0.0f;
        #pragma unroll 4
        for (int i = 0; i < 64; i++) {
            int d = (t >> 6) + i * 4;
            float v = __ldg(xblk + (size_t)d * HWSZ + r);
            acc = fmaf(v, v, acc);
            As[r * PITCH + d] = v;
        }
        part[t] = acc;
    }
    __syncthreads();
    if (t < TM) xn[t] = part[t] + part[t + 64] + part[t + 128] + part[t + 192];

    // ---- preload ALL A fragments (fp16) into registers: 16 kc x 4 regs ---
    uint32_t afr[KC16][4];
    {
        const int r0 = wm * 16 + g;
        #pragma unroll
        for (int kc = 0; kc < KC16; kc++) {
            const int k0 = kc * 16 + 2 * tg;
            const float* base = As + r0 * PITCH + k0;
            float2 v0 = *(const float2*)(base);
            float2 v1 = *(const float2*)(base + 8 * PITCH);
            float2 v2 = *(const float2*)(base + 8);
            float2 v3 = *(const float2*)(base + 8 * PITCH + 8);
            afr[kc][0] = pack_h2(v0.x, v0.y);
            afr[kc][1] = pack_h2(v1.x, v1.y);
            afr[kc][2] = pack_h2(v2.x, v2.y);
            afr[kc][3] = pack_h2(v3.x, v3.y);
        }
    }

    // ---- GEMM over 16 column tiles with fused per-owner top-3 ------------
    float ts[2][3]; int ti[2][3];
    #pragma unroll
    for (int s = 0; s < 2; s++)
        #pragma unroll
        for (int q = 0; q < 3; q++) { ts[s][q] = 3.4e38f; ti[s][q] = 0; }

    for (int nt = 0; nt < NTILES; nt++) {
        const int n0 = nt * NTILE;
        __syncthreads();   // previous tile's consumers done
        // load B tile: 64 codes x 256 floats -> fp16 smem
        #pragma unroll
        for (int i = 0; i < 16; i++) {
            int idx = t + i * 256;         // float4 units
            int n = idx >> 6;
            int kq = (idx & 63) << 2;
            float4 v = __ldg((const float4*)(W + (size_t)(n0 + n) * DDIM + kq));
            uint2 h;
            h.x = pack_h2(v.x, v.y);
            h.y = pack_h2(v.z, v.w);
            *(uint2*)(Bs16 + n * BP + kq) = h;
        }
        __syncthreads();

        float acc[4][4];
        #pragma unroll
        for (int ni = 0; ni < 4; ni++)
            #pragma unroll
            for (int q = 0; q < 4; q++) acc[ni][q] = 0.0f;

        #pragma unroll
        for (int kc = 0; kc < KC16; kc++) {
            const int k0 = kc * 16;
            uint32_t b[4][2];
            #pragma unroll
            for (int ni = 0; ni < 4; ni++) {
                const __half* bp = Bs16 + (wnb + ni * 8 + g) * BP + k0 + 2 * tg;
                b[ni][0] = *(const uint32_t*)(bp);        // k = 2tg, 2tg+1
                b[ni][1] = *(const uint32_t*)(bp + 8);    // k = 2tg+8, 2tg+9
            }
            #pragma unroll
            for (int ni = 0; ni < 4; ni++)
                mma_f16(acc[ni], afr[kc], b[ni][0], b[ni][1]);
        }

        // fold scores into per-half top-3
        #pragma unroll
        for (int half = 0; half < 2; half++) {
            #pragma unroll
            for (int ni = 0; ni < 4; ni++) {
                #pragma unroll
                for (int j = 0; j < 2; j++) {
                    const int c = n0 + wnb + ni * 8 + 2 * tg + j;
                    float v = wn[c] - 2.0f * acc[ni][half * 2 + j];
                    if (v < ts[half][2]) {
                        ts[half][2] = v; ti[half][2] = c;
                        if (ts[half][2] < ts[half][1]) {
                            float f = ts[half][1]; ts[half][1] = ts[half][2]; ts[half][2] = f;
                            int  ii = ti[half][1]; ti[half][1] = ti[half][2]; ti[half][2] = ii;
                        }
                        if (ts[half][1] < ts[half][0]) {
                            float f = ts[half][0]; ts[half][0] = ts[half][1]; ts[half][1] = f;
                            int  ii = ti[half][0]; ti[half][0] = ti[half][1]; ti[half][1] = ii;
                        }
                    }
                }
            }
        }
    }
    __syncthreads();   // B16 region free -> write candidates (aliased)

    {
        const int o = ng * 4 + tg;   // owner 0..7
        #pragma unroll
        for (int half = 0; half < 2; half++) {
            const int r = wm * 16 + half * 8 + g;
            #pragma unroll
            for (int q = 0; q < 3; q++) {
                sc[r * 24 + o * 3 + q] = ts[half][q];
                ci[r * 24 + o * 3 + q] = ti[half][q];
            }
        }
    }
    __syncthreads();

    // ---- thresholded exact fp32 refine (thread-per-row) ------------------
    if (t < TM) {
        const int r = t;
        const float xnr = xn[r];
        // 2nd smallest approx score among 24
        float m1 = 3.4e38f, m2 = 3.4e38f;
        #pragma unroll 8
        for (int q = 0; q < 24; q++) {
            float s = sc[r * 24 + q];
            if (s < m1) { m2 = m1; m1 = s; } else if (s < m2) m2 = s;
        }
        const float thr = m2 + DELTA;
        float b1 = 3.4e38f, b2 = 3.4e38f; int j1 = 0, j2 = 0;
        for (int q = 0; q < 24; q++) {
            if (sc[r * 24 + q] > thr) continue;
            const int c = ci[r * 24 + q];
            const float4* wp = (const float4*)(W + (size_t)c * DDIM);
            const float4* ap = (const float4*)(As + r * PITCH);
            float p = 0.0f;
            #pragma unroll 8
            for (int i = 0; i < 64; i++) {
                float4 wv = __ldg(wp + i);
                float4 av = ap[i];
                p = fmaf(av.x, wv.x, p); p = fmaf(av.y, wv.y, p);
                p = fmaf(av.z, wv.z, p); p = fmaf(av.w, wv.w, p);
            }
            float dist = xnr + wn[c] - 2.0f * p;
            if (dist < b1)      { b2 = b1; j2 = j1; b1 = dist; j1 = c; }
            else if (dist < b2) { b2 = dist; j2 = c; }
        }
        float inv1 = 1.0f / b1, inv2 = 1.0f / b2;
        float nrm = fmaxf(sqrtf(fmaf(inv1, inv1, inv2 * inv2)), 1e-12f);
        float w1o = inv1 / nrm, w2o = inv2 / nrm;
        sw1[r] = w1o; sw2[r] = w2o; si1[r] = j1; si2[r] = j2;
        size_t grow = (size_t)(row0 + r);
        enc[grow * KCODES + j1] = w1o;
        enc[grow * KCODES + j2] = w2o;
        atomicAdd(&g_probs[j1], w1o);
        atomicAdd(&g_probs[j2], w2o);
    }
    __syncthreads();

    // ---- quantized rows (NCHW) + loss partial ----------------------------
    {
        const int r  = t & 63;
        const int d0 = (t >> 6) * 64;
        const float w1o = sw1[r], w2o = sw2[r];
        const float* wr1 = W + (size_t)si1[r] * DDIM;
        const float* wr2 = W + (size_t)si2[r] * DDIM;
        float* qo = out + 1 + (size_t)bb * DDIM * HWSZ + hw0 + r;
        float lacc = 0.0f;
        for (int d = d0; d < d0 + 64; d += 4) {
            float4 wa = __ldg((const float4*)(wr1 + d));
            float4 wb = __ldg((const float4*)(wr2 + d));
            float4 av = *(const float4*)(As + r * PITCH + d);
            float q0 = fmaf(w1o, wa.x, w2o * wb.x);
            float q1 = fmaf(w1o, wa.y, w2o * wb.y);
            float q2 = fmaf(w1o, wa.z, w2o * wb.z);
            float q3 = fmaf(w1o, wa.w, w2o * wb.w);
            float e;
            e = q0 - av.x; lacc = fmaf(e, e, lacc); qo[(size_t)(d + 0) * HWSZ] = q0;
            e = q1 - av.y; lacc = fmaf(e, e, lacc); qo[(size_t)(d + 1) * HWSZ] = q1;
            e = q2 - av.z; lacc = fmaf(e, e, lacc); qo[(size_t)(d + 2) * HWSZ] = q2;
            e = q3 - av.w; lacc = fmaf(e, e, lacc); qo[(size_t)(d + 3) * HWSZ] = q3;
        }
        #pragma unroll
        for (int o = 16; o; o >>= 1) lacc += __shfl_xor_sync(0xffffffffu, lacc, o);
        __syncthreads();
        if ((t & 31) == 0) part[t >> 5] = lacc;
        __syncthreads();
        if (t == 0) {
            float s = 0.0f;
            #pragma unroll
            for (int w = 0; w < 8; w++) s += part[w];
            atomicAdd(&g_loss, s);
        }
    }
}

// ---------------------------------------------------------------------------
// Finalize: perplexity + loss scalars
// ---------------------------------------------------------------------------
__global__ void vq_final(float* __restrict__ out) {
    __shared__ float red[32];
    int t = threadIdx.x;                 // 1024 threads
    float p = g_probs[t] * (1.0f / 32768.0f);
    float e = -p * logf(p + 1e-10f);
    #pragma unroll
    for (int o = 16; o; o >>= 1) e += __shfl_xor_sync(0xffffffffu, e, o);
    if ((t & 31) == 0) red[t >> 5] = e;
    __syncthreads();
    if (t == 0) {
        float s = 0.0f;
        #pragma unroll
        for (int w = 0; w < 32; w++) s += red[w];
        out[(size_t)QELEMS + 1] = expf(s);              // perplexity
        out[0] = 1.25f * g_loss / (float)QELEMS;        // loss
    }
}

// ---------------------------------------------------------------------------
extern "C" void kernel_launch(void* const* d_in, const int* in_sizes, int n_in,
                              void* d_out, int out_size) {
    const float* x = (const float*)d_in[0];   // (32,256,32,32) fp32
    const float* W = (const float*)d_in[1];   // (1024,256) fp32
    float* out = (float*)d_out;
    (void)in_sizes; (void)n_in; (void)out_size;

    cudaFuncSetAttribute(vq_main, cudaFuncAttributeMaxDynamicSharedMemorySize, SMEM_BYTES);
    vq_init<<<128, 256>>>(W);
    vq_main<<<NROWS / TM, NTHREADS, SMEM_BYTES>>>(x, W, out);
    vq_final<<<1, 1024>>>(out);
}

// round 16
// speedup vs baseline: 3.3666x; 1.0454x over previous
#include <cuda_runtime.h>
#include <cuda_fp16.h>
#include <math.h>
#include <stdint.h>

#define DDIM    256
#define HWSZ    1024
#define NROWS   32768
#define KCODES  1024
#define QELEMS  8388608      // 32*256*32*32
#define TM      64
#define NTILE   64           // codes per B tile
#define NTILES  16
#define KC16    16           // 256 / 16 (fp16 K=16 per MMA)
#define NTHREADS 256
#define AP      264          // fp16 A halfs per row: 528B = 33*16 (ldmatrix-aligned, conflict-free)
#define BP      264          // fp16 B halfs per row
#define XP      260          // fp32 Xs floats per row
#define BBYTES  (64 * BP * 2)    // 33792 per buffer

// ---- smem layout (bytes) ----
#define OFF_A16  0                       // 64 x AP fp16           33792
// aliased into A16 region after GEMM:
#define OFF_SC   0                       // sc[64][24] float        6144
#define OFF_CI   6144                    // ci[64][24] int          6144
#define OFF_B    33792                   // 2 x (64 x BP fp16)     67584
// aliased into B region after GEMM:
#define OFF_XS   33792                   // 64 x XP fp32           66560
#define OFF_WN   101376                  // wnorm[1024]             4096
#define OFF_XN   105472                  // xnorm[64]                256
#define OFF_PART 105728                  // reduce scratch[256]     1024
#define OFF_SW1  106752
#define OFF_SW2  107008
#define OFF_SI1  107264
#define OFF_SI2  107520
#define SMEM_BYTES 107776

#define DELTA 0.25f          // approx-score refine threshold

__device__ float g_wnorm[KCODES];
__device__ float g_probs[KCODES];
__device__ float g_loss;
__device__ __align__(16) __half g_W16[KCODES * DDIM];   // fp16 copy of W

// ---------------------------------------------------------------------------
__device__ __forceinline__ void mma_f16(float* d, uint32_t a0, uint32_t a1,
                                        uint32_t a2, uint32_t a3,
                                        uint32_t b0, uint32_t b1) {
    asm volatile(
        "mma.sync.aligned.m16n8k16.row.col.f32.f16.f16.f32 "
        "{%0,%1,%2,%3}, {%4,%5,%6,%7}, {%8,%9}, {%0,%1,%2,%3};"
        : "+f"(d[0]), "+f"(d[1]), "+f"(d[2]), "+f"(d[3])
        : "r"(a0), "r"(a1), "r"(a2), "r"(a3), "r"(b0), "r"(b1));
}
__device__ __forceinline__ uint32_t pack_h2(float lo, float hi) {
    __half2 h = __floats2half2_rn(lo, hi);
    return *reinterpret_cast<uint32_t*>(&h);
}
__device__ __forceinline__ uint32_t smem_u32(const void* p) {
    return (uint32_t)__cvta_generic_to_shared(p);
}

// ---------------------------------------------------------------------------
// Init: zero accumulators, wnorm per code, W -> fp16 copy
// ---------------------------------------------------------------------------
__global__ void vq_init(const float* __restrict__ W) {
    int gt = blockIdx.x * 256 + threadIdx.x;
    if (gt < KCODES) g_probs[gt] = 0.0f;
    if (gt == 0) g_loss = 0.0f;
    int warp = threadIdx.x >> 5, lane = threadIdx.x & 31;
    int code = blockIdx.x * 8 + warp;
    const float4* wp = (const float4*)(W + (size_t)code * DDIM + lane * 8);
    float4 a = wp[0], b = wp[1];
    uint2 h0, h1;
    h0.x = pack_h2(a.x, a.y); h0.y = pack_h2(a.z, a.w);
    h1.x = pack_h2(b.x, b.y); h1.y = pack_h2(b.z, b.w);
    uint2* dst = (uint2*)(g_W16 + (size_t)code * DDIM + lane * 8);
    dst[0] = h0; dst[1] = h1;
    float s = a.x*a.x + a.y*a.y + a.z*a.z + a.w*a.w
            + b.x*b.x + b.y*b.y + b.z*b.z + b.w*b.w;
    #pragma unroll
    for (int o = 16; o; o >>= 1) s += __shfl_xor_sync(0xffffffffu, s, o);
    if (lane == 0) g_wnorm[code] = s;
}

// ---------------------------------------------------------------------------
// Main fused kernel (TM=64, 2 CTAs/SM, cp.async-pipelined fp16 B, ldmatrix)
// ---------------------------------------------------------------------------
__global__ void __launch_bounds__(NTHREADS, 2)
vq_main(const float* __restrict__ x, const float* __restrict__ W,
        float* __restrict__ out) {
    extern __shared__ __align__(1024) char smem[];
    const uint32_t sbase = smem_u32(smem);
    __half* A16  = (__half*)(smem + OFF_A16);
    float*  Xs   = (float*)(smem + OFF_XS);
    float*  sc   = (float*)(smem + OFF_SC);
    int*    ci   = (int*)  (smem + OFF_CI);
    float*  wn   = (float*)(smem + OFF_WN);
    float*  xn   = (float*)(smem + OFF_XN);
    float*  part = (float*)(smem + OFF_PART);
    float*  sw1  = (float*)(smem + OFF_SW1);
    float*  sw2  = (float*)(smem + OFF_SW2);
    int*    si1  = (int*)  (smem + OFF_SI1);
    int*    si2  = (int*)  (smem + OFF_SI2);

    const int t    = threadIdx.x;
    const int lane = t & 31;
    const int warp = t >> 5;
    const int g    = lane >> 2;
    const int tg   = lane & 3;
    const int wm   = warp & 3;           // M warp: rows wm*16 .. +15
    const int ng   = warp >> 2;          // N group (0..1)
    const int wnb  = ng * 32;

    const int row0 = blockIdx.x * TM;
    const int bb   = row0 / HWSZ;
    const int hw0  = row0 % HWSZ;
    const float* xblk = x + (size_t)bb * DDIM * HWSZ + hw0;   // elem (d,r): [d*HWSZ+r]
    float* enc = out + 2 + (size_t)QELEMS;

    // ---- prefetch B tile 0 (fp16, cp.async) -----------------------------
    {
        #pragma unroll
        for (int i = 0; i < 8; i++) {
            int idx = t + i * 256;
            int n = idx >> 5, c = idx & 31;
            uint32_t dst = sbase + OFF_B + (uint32_t)(n * BP + c * 8) * 2;
            const __half* src = g_W16 + (size_t)n * DDIM + c * 8;
            asm volatile("cp.async.cg.shared.global [%0], [%1], 16;" :: "r"(dst), "l"(src));
        }
        asm volatile("cp.async.commit_group;" ::: "memory");
    }

    // stage wnorm
    for (int i = t; i < KCODES; i += NTHREADS) wn[i] = g_wnorm[i];

    // zero this CTA's encodings rows (enc base only 8B-aligned: float2)
    {
        float2 z = make_float2(0.f, 0.f);
        float2* e2 = (float2*)(enc + (size_t)row0 * KCODES);
        #pragma unroll 8
        for (int i = 0; i < 128; i++) e2[t + i * 256] = z;
    }

    // load x -> fp16 A smem [r][d] (pitch 264), accumulate xnorm partials
    {
        int r = t & 63;
        float acc = 0.0f;
        #pragma unroll 4
        for (int i = 0; i < 64; i++) {
            int d = (t >> 6) + i * 4;
            float v = __ldg(xblk + (size_t)d * HWSZ + r);
            acc = fmaf(v, v, acc);
            A16[r * AP + d] = __float2half_rn(v);
        }
        part[t] = acc;
    }
    __syncthreads();
    if (t < TM) xn[t] = part[t] + part[t + 64] + part[t + 128] + part[t + 192];

    // ---- ldmatrix lane addresses (all row starts 16B-aligned: AP*2=528) --
    const uint32_t a_lane = sbase + OFF_A16 +
        (uint32_t)(((wm * 16 + (lane & 15)) * AP + ((lane & 16) ? 8 : 0)) * 2);
    uint32_t b_lane[4];
    #pragma unroll
    for (int ni = 0; ni < 4; ni++)
        b_lane[ni] = sbase + OFF_B +
            (uint32_t)(((wnb + ni * 8 + (lane & 7)) * BP + ((lane & 8) ? 8 : 0)) * 2);

    // ---- pipelined GEMM over 16 column tiles + per-owner top-3 ----------
    float ts[2][3]; int ti[2][3];
    #pragma unroll
    for (int s = 0; s < 2; s++)
        #pragma unroll
        for (int q = 0; q < 3; q++) { ts[s][q] = 3.4e38f; ti[s][q] = 0; }

    for (int nt = 0; nt < NTILES; nt++) {
        // prefetch next tile into other buffer
        if (nt + 1 < NTILES) {
            const int n0n = (nt + 1) * NTILE;
            const uint32_t bo = (uint32_t)(((nt + 1) & 1) * BBYTES);
            #pragma unroll
            for (int i = 0; i < 8; i++) {
                int idx = t + i * 256;
                int n = idx >> 5, c = idx & 31;
                uint32_t dst = sbase + OFF_B + bo + (uint32_t)(n * BP + c * 8) * 2;
                const __half* src = g_W16 + (size_t)(n0n + n) * DDIM + c * 8;
                asm volatile("cp.async.cg.shared.global [%0], [%1], 16;" :: "r"(dst), "l"(src));
            }
            asm volatile("cp.async.commit_group;" ::: "memory");
            asm volatile("cp.async.wait_group 1;" ::: "memory");
        } else {
            asm volatile("cp.async.wait_group 0;" ::: "memory");
        }
        __syncthreads();

        const uint32_t bufo = (uint32_t)((nt & 1) * BBYTES);
        float acc[4][4];
        #pragma unroll
        for (int ni = 0; ni < 4; ni++)
            #pragma unroll
            for (int q = 0; q < 4; q++) acc[ni][q] = 0.0f;

        #pragma unroll
        for (int kc = 0; kc < KC16; kc++) {
            uint32_t a0, a1, a2, a3;
            asm volatile("ldmatrix.sync.aligned.m8n8.x4.shared.b16 {%0,%1,%2,%3}, [%4];"
                : "=r"(a0), "=r"(a1), "=r"(a2), "=r"(a3) : "r"(a_lane + kc * 32));
            #pragma unroll
            for (int ni = 0; ni < 4; ni++) {
                uint32_t b0, b1;
                asm volatile("ldmatrix.sync.aligned.m8n8.x2.shared.b16 {%0,%1}, [%2];"
                    : "=r"(b0), "=r"(b1) : "r"(b_lane[ni] + bufo + kc * 32));
                mma_f16(acc[ni], a0, a1, a2, a3, b0, b1);
            }
        }

        // fold scores into per-half top-3
        const int n0 = nt * NTILE;
        #pragma unroll
        for (int half = 0; half < 2; half++) {
            #pragma unroll
            for (int ni = 0; ni < 4; ni++) {
                #pragma unroll
                for (int j = 0; j < 2; j++) {
                    const int c = n0 + wnb + ni * 8 + 2 * tg + j;
                    float v = wn[c] - 2.0f * acc[ni][half * 2 + j];
                    if (v < ts[half][2]) {
                        ts[half][2] = v; ti[half][2] = c;
                        if (ts[half][2] < ts[half][1]) {
                            float f = ts[half][1]; ts[half][1] = ts[half][2]; ts[half][2] = f;
                            int  ii = ti[half][1]; ti[half][1] = ti[half][2]; ti[half][2] = ii;
                        }
                        if (ts[half][1] < ts[half][0]) {
                            float f = ts[half][0]; ts[half][0] = ts[half][1]; ts[half][1] = f;
                            int  ii = ti[half][0]; ti[half][0] = ti[half][1]; ti[half][1] = ii;
                        }
                    }
                }
            }
        }
        __syncthreads();   // all fragment reads done before buffer rewrite
    }

    // ---- write candidates (A16 region now free), restage x fp32 ---------
    {
        const int o = ng * 4 + tg;   // owner 0..7
        #pragma unroll
        for (int half = 0; half < 2; half++) {
            const int r = wm * 16 + half * 8 + g;
            #pragma unroll
            for (int q = 0; q < 3; q++) {
                sc[r * 24 + o * 3 + q] = ts[half][q];
                ci[r * 24 + o * 3 + q] = ti[half][q];
            }
        }
    }
    {   // reload x (L2-hot) into Xs fp32 (B region now free)
        int r = t & 63;
        #pragma unroll 4
        for (int i = 0; i < 64; i++) {
            int d = (t >> 6) + i * 4;
            Xs[r * XP + d] = __ldg(xblk + (size_t)d * HWSZ + r);
        }
    }
    __syncthreads();

    // ---- thresholded exact fp32 refine (thread-per-row) ------------------
    if (t < TM) {
        const int r = t;
        const float xnr = xn[r];
        float m1 = 3.4e38f, m2 = 3.4e38f;
        #pragma unroll 8
        for (int q = 0; q < 24; q++) {
            float s = sc[r * 24 + q];
            if (s < m1) { m2 = m1; m1 = s; } else if (s < m2) m2 = s;
        }
        const float thr = m2 + DELTA;
        float b1 = 3.4e38f, b2 = 3.4e38f; int j1 = 0, j2 = 0;
        for (int q = 0; q < 24; q++) {
            if (sc[r * 24 + q] > thr) continue;
            const int c = ci[r * 24 + q];
            const float4* wp = (const float4*)(W + (size_t)c * DDIM);
            const float4* ap = (const float4*)(Xs + r * XP);
            float p = 0.0f;
            #pragma unroll 8
            for (int i = 0; i < 64; i++) {
                float4 wv = __ldg(wp + i);
                float4 av = ap[i];
                p = fmaf(av.x, wv.x, p); p = fmaf(av.y, wv.y, p);
                p = fmaf(av.z, wv.z, p); p = fmaf(av.w, wv.w, p);
            }
            float dist = xnr + wn[c] - 2.0f * p;
            if (dist < b1)      { b2 = b1; j2 = j1; b1 = dist; j1 = c; }
            else if (dist < b2) { b2 = dist; j2 = c; }
        }
        float inv1 = 1.0f / b1, inv2 = 1.0f / b2;
        float nrm = fmaxf(sqrtf(fmaf(inv1, inv1, inv2 * inv2)), 1e-12f);
        float w1o = inv1 / nrm, w2o = inv2 / nrm;
        sw1[r] = w1o; sw2[r] = w2o; si1[r] = j1; si2[r] = j2;
        size_t grow = (size_t)(row0 + r);
        enc[grow * KCODES + j1] = w1o;
        enc[grow * KCODES + j2] = w2o;
        atomicAdd(&g_probs[j1], w1o);
        atomicAdd(&g_probs[j2], w2o);
    }
    __syncthreads();

    // ---- quantized rows (NCHW) + loss partial ----------------------------
    {
        const int r  = t & 63;
        const int d0 = (t >> 6) * 64;
        const float w1o = sw1[r], w2o = sw2[r];
        const float* wr1 = W + (size_t)si1[r] * DDIM;
        const float* wr2 = W + (size_t)si2[r] * DDIM;
        float* qo = out + 1 + (size_t)bb * DDIM * HWSZ + hw0 + r;
        float lacc = 0.0f;
        for (int d = d0; d < d0 + 64; d += 4) {
            float4 wa = __ldg((const float4*)(wr1 + d));
            float4 wb = __ldg((const float4*)(wr2 + d));
            float4 av = *(const float4*)(Xs + r * XP + d);
            float q0 = fmaf(w1o, wa.x, w2o * wb.x);
            float q1 = fmaf(w1o, wa.y, w2o * wb.y);
            float q2 = fmaf(w1o, wa.z, w2o * wb.z);
            float q3 = fmaf(w1o, wa.w, w2o * wb.w);
            float e;
            e = q0 - av.x; lacc = fmaf(e, e, lacc); qo[(size_t)(d + 0) * HWSZ] = q0;
            e = q1 - av.y; lacc = fmaf(e, e, lacc); qo[(size_t)(d + 1) * HWSZ] = q1;
            e = q2 - av.z; lacc = fmaf(e, e, lacc); qo[(size_t)(d + 2) * HWSZ] = q2;
            e = q3 - av.w; lacc = fmaf(e, e, lacc); qo[(size_t)(d + 3) * HWSZ] = q3;
        }
        #pragma unroll
        for (int o = 16; o; o >>= 1) lacc += __shfl_xor_sync(0xffffffffu, lacc, o);
        __syncthreads();
        if ((t & 31) == 0) part[t >> 5] = lacc;
        __syncthreads();
        if (t == 0) {
            float s = 0.0f;
            #pragma unroll
            for (int w = 0; w < 8; w++) s += part[w];
            atomicAdd(&g_loss, s);
        }
    }
}

// ---------------------------------------------------------------------------
// Finalize: perplexity + loss scalars
// ---------------------------------------------------------------------------
__global__ void vq_final(float* __restrict__ out) {
    __shared__ float red[32];
    int t = threadIdx.x;                 // 1024 threads
    float p = g_probs[t] * (1.0f / 32768.0f);
    float e = -p * logf(p + 1e-10f);
    #pragma unroll
    for (int o = 16; o; o >>= 1) e += __shfl_xor_sync(0xffffffffu, e, o);
    if ((t & 31) == 0) red[t >> 5] = e;
    __syncthreads();
    if (t == 0) {
        float s = 0.0f;
        #pragma unroll
        for (int w = 0; w < 32; w++) s += red[w];
        out[(size_t)QELEMS + 1] = expf(s);              // perplexity
        out[0] = 1.25f * g_loss / (float)QELEMS;        // loss
    }
}

// ---------------------------------------------------------------------------
extern "C" void kernel_launch(void* const* d_in, const int* in_sizes, int n_in,
                              void* d_out, int out_size) {
    const float* x = (const float*)d_in[0];   // (32,256,32,32) fp32
    const float* W = (const float*)d_in[1];   // (1024,256) fp32
    float* out = (float*)d_out;
    (void)in_sizes; (void)n_in; (void)out_size;

    cudaFuncSetAttribute(vq_main, cudaFuncAttributeMaxDynamicSharedMemorySize, SMEM_BYTES);
    vq_init<<<128, 256>>>(W);
    vq_main<<<NROWS / TM, NTHREADS, SMEM_BYTES>>>(x, W, out);
    vq_final<<<1, 1024>>>(out);
}